// round 2
// baseline (speedup 1.0000x reference)
#include <cuda_runtime.h>
#include <math.h>
#include <stdint.h>

#define NF 65536
#define NB 8
#define JQ 64
#define NSEC 224
#define NCHAN 289
#define LG 768
#define GTAPS 1537          // 2*LG+1
#define KPHI 1024
#define INV_N (1.0f/65536.0f)
#define WINSZ 3332          // 7*256 + 1537 = 3329, padded

// ---------------- static device storage ----------------
static __device__ float2 TW[NF];                 // e^{+2pi i k/N}, double-built
static __device__ float  GF[GTAPS];              // lowpass impulse response
static __device__ float2 d_xf  [  8u*65536u];    // spectra of x
static __device__ float2 d_ping[117440512u];     // 1792*65536
static __device__ float2 d_pong[117440512u];
static __device__ float  d_u1  [ 33554432u];     // 512*65536  |U1| time domain
static __device__ float2 d_u1f [ 33554432u];     // 512*65536  FFT(|U1|)

static __device__ const float2 W16T[16] = {
  { 1.0f, 0.0f},
  { 0.9238795325112867f, 0.3826834323650898f},
  { 0.7071067811865476f, 0.7071067811865476f},
  { 0.3826834323650898f, 0.9238795325112867f},
  { 0.0f, 1.0f},
  {-0.3826834323650898f, 0.9238795325112867f},
  {-0.7071067811865476f, 0.7071067811865476f},
  {-0.9238795325112867f, 0.3826834323650898f},
  {-1.0f, 0.0f},
  {-0.9238795325112867f,-0.3826834323650898f},
  {-0.7071067811865476f,-0.7071067811865476f},
  {-0.3826834323650898f,-0.9238795325112867f},
  { 0.0f,-1.0f},
  { 0.3826834323650898f,-0.9238795325112867f},
  { 0.7071067811865476f,-0.7071067811865476f},
  { 0.9238795325112867f,-0.3826834323650898f}
};

// ---------------- complex helpers ----------------
__device__ __forceinline__ float2 cadd(float2 a, float2 b){ return make_float2(a.x+b.x, a.y+b.y); }
__device__ __forceinline__ float2 csub(float2 a, float2 b){ return make_float2(a.x-b.x, a.y-b.y); }
__device__ __forceinline__ float2 cmul(float2 a, float2 b){ return make_float2(a.x*b.x-a.y*b.y, a.x*b.y+a.y*b.x); }
template<int S> __device__ __forceinline__ float2 mul_i(float2 a){
  return (S>0) ? make_float2(-a.y, a.x) : make_float2(a.y, -a.x);
}
template<int S> __device__ __forceinline__ void dft4(float2&a, float2&b, float2&c, float2&d){
  float2 t0=cadd(a,c), t1=csub(a,c), t2=cadd(b,d), t3=mul_i<S>(csub(b,d));
  a=cadd(t0,t2); c=csub(t0,t2); b=cadd(t1,t3); d=csub(t1,t3);
}
template<int S> __device__ __forceinline__ float2 w16(int m){
  float2 w = W16T[m];
  if (S < 0) w.y = -w.y;
  return w;
}
// natural-order 16-point DFT (sign S: -1 fwd, +1 inv)
template<int S> __device__ __forceinline__ void fft16(float2 v[16]){
  #pragma unroll
  for (int n0=0; n0<4; n0++) dft4<S>(v[n0], v[n0+4], v[n0+8], v[n0+12]);
  #pragma unroll
  for (int n0=1; n0<4; n0++)
    #pragma unroll
    for (int k1=1; k1<4; k1++)
      v[n0+4*k1] = cmul(v[n0+4*k1], w16<S>(n0*k1));
  float2 o[16];
  #pragma unroll
  for (int k1=0; k1<4; k1++){
    float2 a=v[4*k1+0], b=v[4*k1+1], c=v[4*k1+2], d=v[4*k1+3];
    dft4<S>(a,b,c,d);
    o[k1]=a; o[k1+4]=b; o[k1+8]=c; o[k1+12]=d;
  }
  #pragma unroll
  for (int i=0;i<16;i++) v[i]=o[i];
}

// ---------------- setup kernels ----------------
__global__ void k_tw(){
  int k = blockIdx.x*blockDim.x + threadIdx.x;   // 65536 threads
  double a = 6.283185307179586476925286766559 * (double)k / 65536.0;
  TW[k] = make_float2((float)cos(a), (float)sin(a));
}
__global__ void k_g(){
  int i = blockIdx.x*blockDim.x + threadIdx.x;
  if (i >= GTAPS) return;
  int tt = i - LG; if (tt < 0) tt = -tt;
  const float invden = 1.0f/(65536.0f*(0.35f/256.0f));  // 1/(N*sig_phi)
  float acc = 1.0f;                                     // k=0: phi=1
  for (int k=1; k<=KPHI; k++){
    float z = (float)k * invden;
    float p = expf(-0.5f*z*z);
    int m = (k*tt) & 65535;
    acc += 2.0f * p * TW[m].x;
  }
  GF[i] = acc * INV_N;
}

// ---------------- Stockham stage ----------------
// MIN: 0 complex, 1 real(imag=0), 2 xf*psi1/N (first order), 3 u1f*psi2/N (second order)
// MOUT: 0 complex, 1 |.| to float
template<int SIGN, int MIN, int MOUT>
__global__ void __launch_bounds__(256) k_stage(
    const float2* __restrict__ cin, const float* __restrict__ rin,
    float2* __restrict__ cout, float* __restrict__ rout,
    int Ns, int sh)
{
  const int ti = blockIdx.y;
  const int j  = blockIdx.x*256 + threadIdx.x;    // [0,4096)
  float2 v[16];

  if (MIN == 0){
    const float2* p = cin + (size_t)ti*NF + j;
    #pragma unroll
    for (int r=0;r<16;r++) v[r] = p[r*4096];
  } else if (MIN == 1){
    const float* p = rin + (size_t)ti*NF + j;
    #pragma unroll
    for (int r=0;r<16;r++) v[r] = make_float2(p[r*4096], 0.0f);
  } else if (MIN == 2){
    const int b = ti >> 6, ch = ti & 63;
    const float xi   = 0.35f * exp2f(-(float)ch * 0.125f);
    const float invs = 8.0f / xi;
    const float2* p  = cin + (size_t)b*NF;
    #pragma unroll
    for (int r=0;r<16;r++){
      int k = j + r*4096;
      float f = (k < 32768) ? (float)k * INV_N : ((float)k - 65536.0f) * INV_N;
      float z = (f - xi) * invs;
      float g = expf(-0.5f*z*z);
      if (g > 1e-12f){ float2 X = p[k]; float s = g * INV_N; v[r] = make_float2(X.x*s, X.y*s); }
      else v[r] = make_float2(0.0f, 0.0f);
    }
  } else { // MIN == 3
    const int b = ti / NSEC;
    const int s0 = ti - b*NSEC;
    int j2 = 1;
    #pragma unroll
    for (int q=1; q<7; q++) if (s0 >= 4*q*(q+1)) j2 = q+1;
    const int ch = s0 - 4*j2*(j2-1);
    const float xi   = 0.35f * exp2f(-(float)j2);
    const float invs = 1.0f / (0.6f * xi);
    const float2* p  = cin + ((size_t)b*JQ + ch)*NF;
    #pragma unroll
    for (int r=0;r<16;r++){
      int k = j + r*4096;
      float f = (k < 32768) ? (float)k * INV_N : ((float)k - 65536.0f) * INV_N;
      float z = (f - xi) * invs;
      float g = expf(-0.5f*z*z);
      if (g > 1e-12f){ float2 X = p[k]; float s = g * INV_N; v[r] = make_float2(X.x*s, X.y*s); }
      else v[r] = make_float2(0.0f, 0.0f);
    }
  }

  if (Ns > 1){
    const int m = j & (Ns - 1);
    const int step = (NF >> (4 + sh)) * m;
    #pragma unroll
    for (int r=1; r<16; r++){
      float2 w = TW[(r*step) & (NF-1)];
      if (SIGN < 0) w.y = -w.y;
      v[r] = cmul(v[r], w);
    }
  }

  fft16<SIGN>(v);

  const int jd = ((j >> sh) << (sh + 4)) + (j & (Ns - 1));
  if (MOUT == 0){
    float2* p = cout + (size_t)ti*NF + jd;
    #pragma unroll
    for (int r=0;r<16;r++) p[r*Ns] = v[r];
  } else {
    float* p = rout + (size_t)ti*NF + jd;
    #pragma unroll
    for (int r=0;r<16;r++) p[r*Ns] = sqrtf(v[r].x*v[r].x + v[r].y*v[r].y);
  }
}

// ---------------- lowpass conv + log epilogue ----------------
// grid (32, 289, 8), block 256. Each block: 8 outputs (one per warp) of one channel.
__global__ void __launch_bounds__(256) k_conv(
    const float* __restrict__ x, const float* __restrict__ u1,
    const float* __restrict__ u2, float* __restrict__ out)
{
  const int grp = blockIdx.x, c = blockIdx.y, b = blockIdx.z;
  const float* src;
  if (c == 0)       src = x  + (size_t)b*NF;
  else if (c < 65)  src = u1 + ((size_t)b*JQ   + (c-1 ))*NF;
  else              src = u2 + ((size_t)b*NSEC + (c-65))*NF;

  __shared__ float win[WINSZ];
  __shared__ float gs[GTAPS];
  const int tid = threadIdx.x;
  const int w0 = grp*2048 - LG;
  for (int i=tid; i<3329; i+=256) win[i] = src[(w0 + i) & 65535];
  for (int i=tid; i<GTAPS; i+=256) gs[i] = GF[i];
  __syncthreads();

  const int warp = tid >> 5, lane = tid & 31;
  const int off = warp * 256;
  float acc = 0.0f;
  for (int i=lane; i<GTAPS; i+=32) acc += gs[i] * win[off + i];
  #pragma unroll
  for (int d=16; d; d>>=1) acc += __shfl_down_sync(0xffffffffu, acc, d);
  if (lane == 0){
    int n = grp*8 + warp;
    float mag = sqrtf(acc*acc + 1e-8f);
    float val = logf(mag + 1e-8f);
    out[((size_t)b*NCHAN + c)*256 + n] = val;
  }
}

__global__ void k_zero(float* p, int n){
  int i = blockIdx.x*blockDim.x + threadIdx.x;
  if (i < n) p[i] = 0.0f;
}

// ---------------- launch ----------------
extern "C" void kernel_launch(void* const* d_in, const int* in_sizes, int n_in,
                              void* d_out, int out_size)
{
  (void)in_sizes; (void)n_in;
  const float* x = (const float*)d_in[0];
  float* out = (float*)d_out;

  float2 *tw, *xf, *ping, *pong, *u1f;
  float  *u1;
  cudaGetSymbolAddress((void**)&tw,   TW);
  cudaGetSymbolAddress((void**)&xf,   d_xf);
  cudaGetSymbolAddress((void**)&ping, d_ping);
  cudaGetSymbolAddress((void**)&pong, d_pong);
  cudaGetSymbolAddress((void**)&u1,   d_u1);
  cudaGetSymbolAddress((void**)&u1f,  d_u1f);
  (void)tw;
  float* u2 = (float*)pong;   // |U2| aliases pong (written in last SO stage, read by conv)

  k_tw<<<256, 256>>>();
  k_g <<<7,   256>>>();

  // forward FFT of x: 8 transforms
  k_stage<-1,1,0><<<dim3(16,8),   256>>>(nullptr, x,    ping, nullptr,    1, 0);
  k_stage<-1,0,0><<<dim3(16,8),   256>>>(ping, nullptr, pong, nullptr,   16, 4);
  k_stage<-1,0,0><<<dim3(16,8),   256>>>(pong, nullptr, ping, nullptr,  256, 8);
  k_stage<-1,0,0><<<dim3(16,8),   256>>>(ping, nullptr, xf,   nullptr, 4096,12);

  // first-order IFFT(xf*psi1)/N -> |U1|: 512 transforms
  k_stage< 1,2,0><<<dim3(16,512), 256>>>(xf,   nullptr, ping, nullptr,    1, 0);
  k_stage< 1,0,0><<<dim3(16,512), 256>>>(ping, nullptr, pong, nullptr,   16, 4);
  k_stage< 1,0,0><<<dim3(16,512), 256>>>(pong, nullptr, ping, nullptr,  256, 8);
  k_stage< 1,0,1><<<dim3(16,512), 256>>>(ping, nullptr, nullptr, u1,   4096,12);

  // forward FFT of |U1|: 512 transforms
  k_stage<-1,1,0><<<dim3(16,512), 256>>>(nullptr, u1,   ping, nullptr,    1, 0);
  k_stage<-1,0,0><<<dim3(16,512), 256>>>(ping, nullptr, pong, nullptr,   16, 4);
  k_stage<-1,0,0><<<dim3(16,512), 256>>>(pong, nullptr, ping, nullptr,  256, 8);
  k_stage<-1,0,0><<<dim3(16,512), 256>>>(ping, nullptr, u1f,  nullptr, 4096,12);

  // second-order IFFT(U1f*psi2)/N -> |U2|: 1792 transforms
  k_stage< 1,3,0><<<dim3(16,1792),256>>>(u1f,  nullptr, ping, nullptr,    1, 0);
  k_stage< 1,0,0><<<dim3(16,1792),256>>>(ping, nullptr, pong, nullptr,   16, 4);
  k_stage< 1,0,0><<<dim3(16,1792),256>>>(pong, nullptr, ping, nullptr,  256, 8);
  k_stage< 1,0,1><<<dim3(16,1792),256>>>(ping, nullptr, nullptr, u2,   4096,12);

  // lowpass conv + subsample + log  (S0 from x, S1 from |U1|, S2 from |U2|)
  k_conv<<<dim3(32, NCHAN, NB), 256>>>(x, u1, u2, out);

  // imaginary half = zeros
  int half = out_size / 2;
  k_zero<<<(half + 255)/256, 256>>>(out + half, half);
}

// round 3
// speedup vs baseline: 1.2764x; 1.2764x over previous
#include <cuda_runtime.h>
#include <math.h>
#include <stdint.h>

#define NF 65536
#define NB 8
#define JQ 64
#define NSEC 224
#define NCHAN 289
#define LG 768
#define GTAPS 1537
#define KPHI 1024
#define INV_N (1.0f/65536.0f)
#define WINSZ 3332

// ---------------- static device storage ----------------
static __device__ float2 TW[NF];                 // e^{+2pi i k/N}, double-built
static __device__ float  GF[GTAPS];              // lowpass impulse response
static __device__ float2 d_xf  [  8u*65536u];    // spectra of x (swapped layout)
static __device__ float2 d_ping[117440512u];     // 1792*65536
static __device__ float2 d_pong[117440512u];
static __device__ float  d_u1  [ 33554432u];     // 512*65536  |U1| time domain
static __device__ float2 d_u1f [ 33554432u];     // 512*65536  FFT(|U1|) (swapped layout)

static __device__ const float2 W16T[16] = {
  { 1.0f, 0.0f},
  { 0.9238795325112867f, 0.3826834323650898f},
  { 0.7071067811865476f, 0.7071067811865476f},
  { 0.3826834323650898f, 0.9238795325112867f},
  { 0.0f, 1.0f},
  {-0.3826834323650898f, 0.9238795325112867f},
  {-0.7071067811865476f, 0.7071067811865476f},
  {-0.9238795325112867f, 0.3826834323650898f},
  {-1.0f, 0.0f},
  {-0.9238795325112867f,-0.3826834323650898f},
  {-0.7071067811865476f,-0.7071067811865476f},
  {-0.3826834323650898f,-0.9238795325112867f},
  { 0.0f,-1.0f},
  { 0.3826834323650898f,-0.9238795325112867f},
  { 0.7071067811865476f,-0.7071067811865476f},
  { 0.9238795325112867f,-0.3826834323650898f}
};

// ---------------- complex helpers ----------------
__device__ __forceinline__ float2 cadd(float2 a, float2 b){ return make_float2(a.x+b.x, a.y+b.y); }
__device__ __forceinline__ float2 csub(float2 a, float2 b){ return make_float2(a.x-b.x, a.y-b.y); }
__device__ __forceinline__ float2 cmul(float2 a, float2 b){ return make_float2(a.x*b.x-a.y*b.y, a.x*b.y+a.y*b.x); }
template<int S> __device__ __forceinline__ float2 mul_i(float2 a){
  return (S>0) ? make_float2(-a.y, a.x) : make_float2(a.y, -a.x);
}
template<int S> __device__ __forceinline__ void dft4(float2&a, float2&b, float2&c, float2&d){
  float2 t0=cadd(a,c), t1=csub(a,c), t2=cadd(b,d), t3=mul_i<S>(csub(b,d));
  a=cadd(t0,t2); c=csub(t0,t2); b=cadd(t1,t3); d=csub(t1,t3);
}
template<int S> __device__ __forceinline__ float2 w16(int m){
  float2 w = W16T[m];
  if (S < 0) w.y = -w.y;
  return w;
}
template<int S> __device__ __forceinline__ void fft16(float2 v[16]){
  #pragma unroll
  for (int n0=0; n0<4; n0++) dft4<S>(v[n0], v[n0+4], v[n0+8], v[n0+12]);
  #pragma unroll
  for (int n0=1; n0<4; n0++)
    #pragma unroll
    for (int k1=1; k1<4; k1++)
      v[n0+4*k1] = cmul(v[n0+4*k1], w16<S>(n0*k1));
  float2 o[16];
  #pragma unroll
  for (int k1=0; k1<4; k1++){
    float2 a=v[4*k1+0], b=v[4*k1+1], c=v[4*k1+2], d=v[4*k1+3];
    dft4<S>(a,b,c,d);
    o[k1]=a; o[k1+4]=b; o[k1+8]=c; o[k1+12]=d;
  }
  #pragma unroll
  for (int i=0;i<16;i++) v[i]=o[i];
}

// 256-point FFT across registers+smem. Thread lane i in [0,16): holds
// v[r] = data[r*16 + i] on entry, v[k2] = X[k2*16 + i] on exit.
// sm must point to a 256-entry (padded row) region private to this FFT.
// Caller must __syncthreads() between consecutive calls reusing smem.
template<int S> __device__ __forceinline__ void fft256_regs(float2 v[16], int i, float2* sm){
  fft16<S>(v);
  #pragma unroll
  for (int k1=1;k1<16;k1++){
    float2 w = TW[(i*k1*256)&65535];
    if (S<0) w.y = -w.y;
    v[k1] = cmul(v[k1], w);
  }
  #pragma unroll
  for (int k1=0;k1<16;k1++) sm[k1*16+i] = v[k1];
  __syncthreads();
  #pragma unroll
  for (int n0=0;n0<16;n0++) v[n0] = sm[i*16+n0];
  fft16<S>(v);
}

// ---------------- setup kernels ----------------
__global__ void k_tw(){
  int k = blockIdx.x*blockDim.x + threadIdx.x;
  double a = 6.283185307179586476925286766559 * (double)k / 65536.0;
  TW[k] = make_float2((float)cos(a), (float)sin(a));
}
__global__ void k_g(){
  int i = blockIdx.x*blockDim.x + threadIdx.x;
  if (i >= GTAPS) return;
  int tt = i - LG; if (tt < 0) tt = -tt;
  const float invden = 1.0f/(65536.0f*(0.35f/256.0f));
  float acc = 1.0f;
  for (int k=1; k<=KPHI; k++){
    float z = (float)k * invden;
    float p = expf(-0.5f*z*z);
    int m = (k*tt) & 65535;
    acc += 2.0f * p * TW[m].x;
  }
  GF[i] = acc * INV_N;
}

// ---------------- FFT pass kernels ----------------
// Forward pass 1 over strided (column) axis, real input x, fwd twiddle on store.
__global__ void __launch_bounds__(256) k_fwd_col_x(const float* __restrict__ x,
                                                   float2* __restrict__ out)
{
  __shared__ float2 sm[16*257];
  const int f = threadIdx.x & 15, i = threadIdx.x >> 4;
  const int col = blockIdx.x*16 + f;
  const size_t base = (size_t)blockIdx.y * NF;
  float2 v[16];
  #pragma unroll
  for (int r=0;r<16;r++) v[r] = make_float2(x[base + (r*16+i)*256 + col], 0.0f);
  fft256_regs<-1>(v, i, sm + f*257);
  #pragma unroll
  for (int k2=0;k2<16;k2++){
    int K1 = k2*16 + i;
    float2 w = TW[(col*K1)&65535]; w.y = -w.y;
    out[base + K1*256 + col] = cmul(v[k2], w);
  }
}

// Forward pass 2 over contiguous (row) axis. Output stays in swapped layout:
// memory [K1][k2c] <-> frequency k = k2c*256 + K1.
__global__ void __launch_bounds__(256) k_fwd_row(const float2* __restrict__ in,
                                                 float2* __restrict__ out)
{
  __shared__ float2 sm[16*257];
  const int i = threadIdx.x & 15, f = threadIdx.x >> 4;
  const int row = blockIdx.x*16 + f;
  const size_t base = (size_t)blockIdx.y * NF;
  float2 v[16];
  #pragma unroll
  for (int r=0;r<16;r++) v[r] = in[base + row*256 + r*16 + i];
  fft256_regs<-1>(v, i, sm + f*257);
  #pragma unroll
  for (int k2=0;k2<16;k2++) out[base + row*256 + k2*16 + i] = v[k2];
}

// Inverse pass A over contiguous axis with fused filter*1/N on load (pruned)
// and inverse inter-pass twiddle on store. FILT=1: psi1 from xf. FILT=2: psi2 from u1f.
template<int FILT>
__global__ void __launch_bounds__(256) k_invA(const float2* __restrict__ in,
                                              float2* __restrict__ out)
{
  __shared__ float2 sm[16*257];
  const int i = threadIdx.x & 15, f = threadIdx.x >> 4;
  const int K1 = blockIdx.x*16 + f;
  const int ti = blockIdx.y;

  float xi, invs;
  const float2* src;
  if (FILT == 1){
    const int b = ti >> 6, ch = ti & 63;
    xi   = 0.35f * exp2f(-(float)ch * 0.125f);
    invs = 8.0f / xi;
    src  = in + (size_t)b*NF;
  } else {
    const int b = ti / NSEC;
    const int s0 = ti - b*NSEC;
    int j2 = 1;
    #pragma unroll
    for (int q=1; q<7; q++) if (s0 >= 4*q*(q+1)) j2 = q+1;
    const int ch = s0 - 4*j2*(j2-1);
    xi   = 0.35f * exp2f(-(float)j2);
    invs = 1.0f / (0.6f * xi);
    src  = in + ((size_t)b*JQ + ch)*NF;
  }

  float2 v[16];
  #pragma unroll
  for (int r=0;r<16;r++){
    int k2c = r*16 + i;
    int k = k2c*256 + K1;
    float fn = (k < 32768) ? (float)k * INV_N : ((float)k - 65536.0f) * INV_N;
    float z = (fn - xi) * invs;
    float g = expf(-0.5f*z*z);
    if (g > 1e-12f){
      float2 X = src[K1*256 + k2c];
      float s = g * INV_N;
      v[r] = make_float2(X.x*s, X.y*s);
    } else v[r] = make_float2(0.0f, 0.0f);
  }
  fft256_regs<1>(v, i, sm + f*257);
  #pragma unroll
  for (int k2=0;k2<16;k2++){
    int n2 = k2*16 + i;
    out[(size_t)ti*NF + K1*256 + n2] = cmul(v[k2], TW[(n2*K1)&65535]);
  }
}

// First-order pass B fused with forward column pass of FFT(|U1|):
// col IFFT over K1 -> |.| -> store u1 -> col FFT over n1 -> fwd twiddle -> out.
__global__ void __launch_bounds__(256) k_fo_b(const float2* __restrict__ T,
                                              float* __restrict__ u1,
                                              float2* __restrict__ out)
{
  __shared__ float2 sm[16*257];
  const int f = threadIdx.x & 15, i = threadIdx.x >> 4;
  const int n2 = blockIdx.x*16 + f;
  const size_t base = (size_t)blockIdx.y * NF;
  float2 v[16];
  #pragma unroll
  for (int r=0;r<16;r++) v[r] = T[base + (r*16+i)*256 + n2];
  fft256_regs<1>(v, i, sm + f*257);
  float u[16];
  #pragma unroll
  for (int k2=0;k2<16;k2++){
    u[k2] = sqrtf(v[k2].x*v[k2].x + v[k2].y*v[k2].y);
    u1[base + (k2*16+i)*256 + n2] = u[k2];
  }
  __syncthreads();
  #pragma unroll
  for (int r=0;r<16;r++) v[r] = make_float2(u[r], 0.0f);
  fft256_regs<-1>(v, i, sm + f*257);
  #pragma unroll
  for (int k2=0;k2<16;k2++){
    int K1 = k2*16 + i;
    float2 w = TW[(n2*K1)&65535]; w.y = -w.y;
    out[base + K1*256 + n2] = cmul(v[k2], w);
  }
}

// Second-order pass B: col IFFT over K1, modulus to real output.
__global__ void __launch_bounds__(256) k_invB_abs(const float2* __restrict__ T,
                                                  float* __restrict__ u2)
{
  __shared__ float2 sm[16*257];
  const int f = threadIdx.x & 15, i = threadIdx.x >> 4;
  const int n2 = blockIdx.x*16 + f;
  const size_t base = (size_t)blockIdx.y * NF;
  float2 v[16];
  #pragma unroll
  for (int r=0;r<16;r++) v[r] = T[base + (r*16+i)*256 + n2];
  fft256_regs<1>(v, i, sm + f*257);
  #pragma unroll
  for (int k2=0;k2<16;k2++)
    u2[base + (k2*16+i)*256 + n2] = sqrtf(v[k2].x*v[k2].x + v[k2].y*v[k2].y);
}

// ---------------- lowpass conv + log epilogue ----------------
__global__ void __launch_bounds__(256) k_conv(
    const float* __restrict__ x, const float* __restrict__ u1,
    const float* __restrict__ u2, float* __restrict__ out)
{
  const int grp = blockIdx.x, c = blockIdx.y, b = blockIdx.z;
  const float* src;
  if (c == 0)       src = x  + (size_t)b*NF;
  else if (c < 65)  src = u1 + ((size_t)b*JQ   + (c-1 ))*NF;
  else              src = u2 + ((size_t)b*NSEC + (c-65))*NF;

  __shared__ float win[WINSZ];
  __shared__ float gs[GTAPS];
  const int tid = threadIdx.x;
  const int w0 = grp*2048 - LG;
  for (int i=tid; i<3329; i+=256) win[i] = src[(w0 + i) & 65535];
  for (int i=tid; i<GTAPS; i+=256) gs[i] = GF[i];
  __syncthreads();

  const int warp = tid >> 5, lane = tid & 31;
  const int off = warp * 256;
  float acc = 0.0f;
  for (int i=lane; i<GTAPS; i+=32) acc += gs[i] * win[off + i];
  #pragma unroll
  for (int d=16; d; d>>=1) acc += __shfl_down_sync(0xffffffffu, acc, d);
  if (lane == 0){
    int n = grp*8 + warp;
    float mag = sqrtf(acc*acc + 1e-8f);
    out[((size_t)b*NCHAN + c)*256 + n] = logf(mag + 1e-8f);
  }
}

__global__ void k_zero(float* p, int n){
  int i = blockIdx.x*blockDim.x + threadIdx.x;
  if (i < n) p[i] = 0.0f;
}

// ---------------- launch ----------------
extern "C" void kernel_launch(void* const* d_in, const int* in_sizes, int n_in,
                              void* d_out, int out_size)
{
  (void)in_sizes; (void)n_in;
  const float* x = (const float*)d_in[0];
  float* out = (float*)d_out;

  float2 *xf, *ping, *pong, *u1f;
  float  *u1;
  cudaGetSymbolAddress((void**)&xf,   d_xf);
  cudaGetSymbolAddress((void**)&ping, d_ping);
  cudaGetSymbolAddress((void**)&pong, d_pong);
  cudaGetSymbolAddress((void**)&u1,   d_u1);
  cudaGetSymbolAddress((void**)&u1f,  d_u1f);
  float* u2 = (float*)pong;   // aliased: pong free once u1f is built

  k_tw<<<256, 256>>>();
  k_g <<<7,   256>>>();

  // forward FFT of x (8 transforms): 2 passes
  k_fwd_col_x<<<dim3(16,8),    256>>>(x, ping);
  k_fwd_row  <<<dim3(16,8),    256>>>(ping, xf);

  // first order: filtered inverse pass A, then fused (IFFT col + |.| + FFT col)
  k_invA<1>  <<<dim3(16,512),  256>>>(xf, ping);
  k_fo_b     <<<dim3(16,512),  256>>>(ping, u1, pong);
  k_fwd_row  <<<dim3(16,512),  256>>>(pong, u1f);

  // second order: filtered inverse pass A + inverse pass B with modulus
  k_invA<2>  <<<dim3(16,1792), 256>>>(u1f, ping);
  k_invB_abs <<<dim3(16,1792), 256>>>(ping, u2);

  // lowpass conv + subsample + log
  k_conv<<<dim3(32, NCHAN, NB), 256>>>(x, u1, u2, out);

  // imaginary half = zeros
  int half = out_size / 2;
  k_zero<<<(half + 255)/256, 256>>>(out + half, half);
}

// round 4
// speedup vs baseline: 1.7095x; 1.3393x over previous
#include <cuda_runtime.h>
#include <math.h>
#include <stdint.h>

#define NF 65536
#define NB 8
#define JQ 64
#define NSEC 224
#define NCHAN 289
#define LG 768
#define GTAPS 1537
#define KPHI 1024
#define INV_N (1.0f/65536.0f)

// ---------------- static device storage ----------------
static __device__ float2 TW[NF];                 // e^{+2pi i k/N}, double-built
static __device__ float  GF[GTAPS];              // lowpass impulse response
static __device__ float2 d_xf  [  8u*65536u];    // spectra of x (swapped layout)
static __device__ float2 d_ping[117440512u];     // 1792*65536
static __device__ float2 d_pong[117440512u];
static __device__ float  d_u1  [ 33554432u];     // 512*65536  |U1| time domain
static __device__ float2 d_u1f [ 33554432u];     // 512*65536  FFT(|U1|) (swapped layout)

static __device__ const float2 W16T[16] = {
  { 1.0f, 0.0f},
  { 0.9238795325112867f, 0.3826834323650898f},
  { 0.7071067811865476f, 0.7071067811865476f},
  { 0.3826834323650898f, 0.9238795325112867f},
  { 0.0f, 1.0f},
  {-0.3826834323650898f, 0.9238795325112867f},
  {-0.7071067811865476f, 0.7071067811865476f},
  {-0.9238795325112867f, 0.3826834323650898f},
  {-1.0f, 0.0f},
  {-0.9238795325112867f,-0.3826834323650898f},
  {-0.7071067811865476f,-0.7071067811865476f},
  {-0.3826834323650898f,-0.9238795325112867f},
  { 0.0f,-1.0f},
  { 0.3826834323650898f,-0.9238795325112867f},
  { 0.7071067811865476f,-0.7071067811865476f},
  { 0.9238795325112867f,-0.3826834323650898f}
};

// ---------------- complex helpers ----------------
__device__ __forceinline__ float2 cadd(float2 a, float2 b){ return make_float2(a.x+b.x, a.y+b.y); }
__device__ __forceinline__ float2 csub(float2 a, float2 b){ return make_float2(a.x-b.x, a.y-b.y); }
__device__ __forceinline__ float2 cmul(float2 a, float2 b){ return make_float2(a.x*b.x-a.y*b.y, a.x*b.y+a.y*b.x); }
template<int S> __device__ __forceinline__ float2 mul_i(float2 a){
  return (S>0) ? make_float2(-a.y, a.x) : make_float2(a.y, -a.x);
}
template<int S> __device__ __forceinline__ void dft4(float2&a, float2&b, float2&c, float2&d){
  float2 t0=cadd(a,c), t1=csub(a,c), t2=cadd(b,d), t3=mul_i<S>(csub(b,d));
  a=cadd(t0,t2); c=csub(t0,t2); b=cadd(t1,t3); d=csub(t1,t3);
}
template<int S> __device__ __forceinline__ float2 w16(int m){
  float2 w = W16T[m];
  if (S < 0) w.y = -w.y;
  return w;
}
template<int S> __device__ __forceinline__ void fft16(float2 v[16]){
  #pragma unroll
  for (int n0=0; n0<4; n0++) dft4<S>(v[n0], v[n0+4], v[n0+8], v[n0+12]);
  #pragma unroll
  for (int n0=1; n0<4; n0++)
    #pragma unroll
    for (int k1=1; k1<4; k1++)
      v[n0+4*k1] = cmul(v[n0+4*k1], w16<S>(n0*k1));
  float2 o[16];
  #pragma unroll
  for (int k1=0; k1<4; k1++){
    float2 a=v[4*k1+0], b=v[4*k1+1], c=v[4*k1+2], d=v[4*k1+3];
    dft4<S>(a,b,c,d);
    o[k1]=a; o[k1+4]=b; o[k1+8]=c; o[k1+12]=d;
  }
  #pragma unroll
  for (int i=0;i<16;i++) v[i]=o[i];
}

// 256-point FFT, padded-row transpose (conflict-free when the FFT-slot index f
// lives in the LOW 4 bits of threadIdx). sm row stride 257.
template<int S> __device__ __forceinline__ void fft256_pad(float2 v[16], int i, float2* sm){
  fft16<S>(v);
  #pragma unroll
  for (int k1=1;k1<16;k1++){
    float2 w = TW[(i*k1*256)&65535];
    if (S<0) w.y = -w.y;
    v[k1] = cmul(v[k1], w);
  }
  #pragma unroll
  for (int k1=0;k1<16;k1++) sm[k1*16+i] = v[k1];
  __syncthreads();
  #pragma unroll
  for (int n0=0;n0<16;n0++) v[n0] = sm[i*16+n0];
  fft16<S>(v);
}

// 256-point FFT, swizzled transpose (conflict-free when the lane index i lives
// in the LOW 4 bits of threadIdx). sm row stride 256.
template<int S> __device__ __forceinline__ void fft256_swz(float2 v[16], int i, float2* sm){
  fft16<S>(v);
  #pragma unroll
  for (int k1=1;k1<16;k1++){
    float2 w = TW[(i*k1*256)&65535];
    if (S<0) w.y = -w.y;
    v[k1] = cmul(v[k1], w);
  }
  #pragma unroll
  for (int k1=0;k1<16;k1++) sm[k1*16 + ((i+k1)&15)] = v[k1];
  __syncthreads();
  #pragma unroll
  for (int n0=0;n0<16;n0++) v[n0] = sm[i*16 + ((n0+i)&15)];
  fft16<S>(v);
}

// ---------------- setup kernels ----------------
__global__ void k_tw(){
  int k = blockIdx.x*blockDim.x + threadIdx.x;
  double a = 6.283185307179586476925286766559 * (double)k / 65536.0;
  TW[k] = make_float2((float)cos(a), (float)sin(a));
}
__global__ void k_g(){
  int i = blockIdx.x*blockDim.x + threadIdx.x;
  if (i >= GTAPS) return;
  int tt = i - LG; if (tt < 0) tt = -tt;
  const float invden = 1.0f/(65536.0f*(0.35f/256.0f));
  float acc = 1.0f;
  for (int k=1; k<=KPHI; k++){
    float z = (float)k * invden;
    float p = expf(-0.5f*z*z);
    int m = (k*tt) & 65535;
    acc += 2.0f * p * TW[m].x;
  }
  GF[i] = acc * INV_N;
}

// ---------------- FFT pass kernels ----------------
// Forward pass 1 over strided (column) axis, real input x. f-low mapping.
__global__ void __launch_bounds__(256) k_fwd_col_x(const float* __restrict__ x,
                                                   float2* __restrict__ out)
{
  __shared__ float2 sm[16*257];
  const int f = threadIdx.x & 15, i = threadIdx.x >> 4;
  const int col = blockIdx.x*16 + f;
  const size_t base = (size_t)blockIdx.y * NF;
  float2 v[16];
  #pragma unroll
  for (int r=0;r<16;r++) v[r] = make_float2(x[base + (r*16+i)*256 + col], 0.0f);
  fft256_pad<-1>(v, i, sm + f*257);
  #pragma unroll
  for (int k2=0;k2<16;k2++){
    int K1 = k2*16 + i;
    float2 w = TW[(col*K1)&65535]; w.y = -w.y;
    out[base + K1*256 + col] = cmul(v[k2], w);
  }
}

// Forward pass 2 over contiguous (row) axis. i-low mapping -> swizzled smem.
__global__ void __launch_bounds__(256) k_fwd_row(const float2* __restrict__ in,
                                                 float2* __restrict__ out)
{
  __shared__ float2 sm[16*256];
  const int i = threadIdx.x & 15, f = threadIdx.x >> 4;
  const int row = blockIdx.x*16 + f;
  const size_t base = (size_t)blockIdx.y * NF;
  float2 v[16];
  #pragma unroll
  for (int r=0;r<16;r++) v[r] = in[base + row*256 + r*16 + i];
  fft256_swz<-1>(v, i, sm + f*256);
  #pragma unroll
  for (int k2=0;k2<16;k2++) out[base + row*256 + k2*16 + i] = v[k2];
}

// Inverse pass A over contiguous axis, fused pruned filter*1/N on load,
// inverse inter-pass twiddle on store. i-low mapping -> swizzled smem.
// FILT=1: psi1 from xf. FILT=2: psi2 from u1f.
template<int FILT>
__global__ void __launch_bounds__(256) k_invA(const float2* __restrict__ in,
                                              float2* __restrict__ out)
{
  __shared__ float2 sm[16*256];
  const int i = threadIdx.x & 15, f = threadIdx.x >> 4;
  const int K1 = blockIdx.x*16 + f;
  const int ti = blockIdx.y;

  float xi, invs;
  const float2* src;
  if (FILT == 1){
    const int b = ti >> 6, ch = ti & 63;
    xi   = 0.35f * exp2f(-(float)ch * 0.125f);
    invs = 8.0f / xi;
    src  = in + (size_t)b*NF;
  } else {
    const int b = ti / NSEC;
    const int s0 = ti - b*NSEC;
    int j2 = 1;
    #pragma unroll
    for (int q=1; q<7; q++) if (s0 >= 4*q*(q+1)) j2 = q+1;
    const int ch = s0 - 4*j2*(j2-1);
    xi   = 0.35f * exp2f(-(float)j2);
    invs = 1.0f / (0.6f * xi);
    src  = in + ((size_t)b*JQ + ch)*NF;
  }

  float2 v[16];
  #pragma unroll
  for (int r=0;r<16;r++){
    int k2c = r*16 + i;
    int k = k2c*256 + K1;
    float fn = (k < 32768) ? (float)k * INV_N : ((float)k - 65536.0f) * INV_N;
    float z = (fn - xi) * invs;
    float g = expf(-0.5f*z*z);
    if (g > 1e-12f){
      float2 X = src[K1*256 + k2c];
      float s = g * INV_N;
      v[r] = make_float2(X.x*s, X.y*s);
    } else v[r] = make_float2(0.0f, 0.0f);
  }
  fft256_swz<1>(v, i, sm + f*256);
  #pragma unroll
  for (int k2=0;k2<16;k2++){
    int n2 = k2*16 + i;
    out[(size_t)ti*NF + K1*256 + n2] = cmul(v[k2], TW[(n2*K1)&65535]);
  }
}

// First-order pass B fused with forward column pass of FFT(|U1|). f-low mapping.
__global__ void __launch_bounds__(256) k_fo_b(const float2* __restrict__ T,
                                              float* __restrict__ u1,
                                              float2* __restrict__ out)
{
  __shared__ float2 sm[16*257];
  const int f = threadIdx.x & 15, i = threadIdx.x >> 4;
  const int n2 = blockIdx.x*16 + f;
  const size_t base = (size_t)blockIdx.y * NF;
  float2 v[16];
  #pragma unroll
  for (int r=0;r<16;r++) v[r] = T[base + (r*16+i)*256 + n2];
  fft256_pad<1>(v, i, sm + f*257);
  float u[16];
  #pragma unroll
  for (int k2=0;k2<16;k2++){
    u[k2] = sqrtf(v[k2].x*v[k2].x + v[k2].y*v[k2].y);
    u1[base + (k2*16+i)*256 + n2] = u[k2];
  }
  __syncthreads();
  #pragma unroll
  for (int r=0;r<16;r++) v[r] = make_float2(u[r], 0.0f);
  fft256_pad<-1>(v, i, sm + f*257);
  #pragma unroll
  for (int k2=0;k2<16;k2++){
    int K1 = k2*16 + i;
    float2 w = TW[(n2*K1)&65535]; w.y = -w.y;
    out[base + K1*256 + n2] = cmul(v[k2], w);
  }
}

// Second-order pass B: col IFFT, modulus to real output. f-low mapping.
__global__ void __launch_bounds__(256) k_invB_abs(const float2* __restrict__ T,
                                                  float* __restrict__ u2)
{
  __shared__ float2 sm[16*257];
  const int f = threadIdx.x & 15, i = threadIdx.x >> 4;
  const int n2 = blockIdx.x*16 + f;
  const size_t base = (size_t)blockIdx.y * NF;
  float2 v[16];
  #pragma unroll
  for (int r=0;r<16;r++) v[r] = T[base + (r*16+i)*256 + n2];
  fft256_pad<1>(v, i, sm + f*257);
  #pragma unroll
  for (int k2=0;k2<16;k2++)
    u2[base + (k2*16+i)*256 + n2] = sqrtf(v[k2].x*v[k2].x + v[k2].y*v[k2].y);
}

// ---------------- lowpass conv + log epilogue ----------------
// grid (8, 289, 8): each block computes 32 outputs of one channel.
#define CONV_OUT 32
#define CONV_WIN ((CONV_OUT-1)*256 + GTAPS)   // 9473
__global__ void __launch_bounds__(256) k_conv(
    const float* __restrict__ x, const float* __restrict__ u1,
    const float* __restrict__ u2, float* __restrict__ out)
{
  const int grp = blockIdx.x, c = blockIdx.y, b = blockIdx.z;
  const float* src;
  if (c == 0)       src = x  + (size_t)b*NF;
  else if (c < 65)  src = u1 + ((size_t)b*JQ   + (c-1 ))*NF;
  else              src = u2 + ((size_t)b*NSEC + (c-65))*NF;

  __shared__ float win[CONV_WIN + 3];
  __shared__ float gs[GTAPS];
  const int tid = threadIdx.x;
  const int w0 = grp*(CONV_OUT*256) - LG;
  for (int i=tid; i<CONV_WIN; i+=256) win[i] = src[(w0 + i) & 65535];
  for (int i=tid; i<GTAPS; i+=256) gs[i] = GF[i];
  __syncthreads();

  const int warp = tid >> 5, lane = tid & 31;
  #pragma unroll
  for (int oo=0; oo<CONV_OUT/8; oo++){
    const int o = warp*(CONV_OUT/8) + oo;
    const int off = o * 256;
    float acc = 0.0f;
    for (int i=lane; i<GTAPS; i+=32) acc += gs[i] * win[off + i];
    #pragma unroll
    for (int d=16; d; d>>=1) acc += __shfl_down_sync(0xffffffffu, acc, d);
    if (lane == 0){
      int n = grp*CONV_OUT + o;
      float mag = sqrtf(acc*acc + 1e-8f);
      out[((size_t)b*NCHAN + c)*256 + n] = logf(mag + 1e-8f);
    }
  }
}

__global__ void k_zero(float* p, int n){
  int i = blockIdx.x*blockDim.x + threadIdx.x;
  if (i < n) p[i] = 0.0f;
}

// ---------------- launch ----------------
extern "C" void kernel_launch(void* const* d_in, const int* in_sizes, int n_in,
                              void* d_out, int out_size)
{
  (void)in_sizes; (void)n_in;
  const float* x = (const float*)d_in[0];
  float* out = (float*)d_out;

  float2 *xf, *ping, *pong, *u1f;
  float  *u1;
  cudaGetSymbolAddress((void**)&xf,   d_xf);
  cudaGetSymbolAddress((void**)&ping, d_ping);
  cudaGetSymbolAddress((void**)&pong, d_pong);
  cudaGetSymbolAddress((void**)&u1,   d_u1);
  cudaGetSymbolAddress((void**)&u1f,  d_u1f);
  float* u2 = (float*)pong;   // aliased: pong free once u1f is built

  k_tw<<<256, 256>>>();
  k_g <<<7,   256>>>();

  // forward FFT of x (8 transforms)
  k_fwd_col_x<<<dim3(16,8),    256>>>(x, ping);
  k_fwd_row  <<<dim3(16,8),    256>>>(ping, xf);

  // first order
  k_invA<1>  <<<dim3(16,512),  256>>>(xf, ping);
  k_fo_b     <<<dim3(16,512),  256>>>(ping, u1, pong);
  k_fwd_row  <<<dim3(16,512),  256>>>(pong, u1f);

  // second order
  k_invA<2>  <<<dim3(16,1792), 256>>>(u1f, ping);
  k_invB_abs <<<dim3(16,1792), 256>>>(ping, u2);

  // lowpass conv + subsample + log
  k_conv<<<dim3(8, NCHAN, NB), 256>>>(x, u1, u2, out);

  // imaginary half = zeros
  int half = out_size / 2;
  k_zero<<<(half + 255)/256, 256>>>(out + half, half);
}

// round 5
// speedup vs baseline: 1.8548x; 1.0850x over previous
#include <cuda_runtime.h>
#include <math.h>
#include <stdint.h>

#define NF 65536
#define NB 8
#define JQ 64
#define NSEC 224
#define NCHAN 289
#define LG 768
#define GTAPS 1537
#define KPHI 1024
#define INV_N (1.0f/65536.0f)

// ---------------- static device storage ----------------
static __device__ float2 TW[NF];
static __device__ float  GF[GTAPS];
static __device__ float2 d_xf  [  8u*65536u];
static __device__ float2 d_ping[117440512u];     // 1792*65536
static __device__ float2 d_pong[117440512u];
static __device__ float2 d_u1f [ 33554432u];     // 512*65536
static __device__ float  d_sp1 [  512u*4096u];   // per-block lowpass partials (FO)
static __device__ float  d_sp2 [ 1792u*4096u];   // per-block lowpass partials (SO)

static __device__ const float2 W16T[16] = {
  { 1.0f, 0.0f},
  { 0.9238795325112867f, 0.3826834323650898f},
  { 0.7071067811865476f, 0.7071067811865476f},
  { 0.3826834323650898f, 0.9238795325112867f},
  { 0.0f, 1.0f},
  {-0.3826834323650898f, 0.9238795325112867f},
  {-0.7071067811865476f, 0.7071067811865476f},
  {-0.9238795325112867f, 0.3826834323650898f},
  {-1.0f, 0.0f},
  {-0.9238795325112867f,-0.3826834323650898f},
  {-0.7071067811865476f,-0.7071067811865476f},
  {-0.3826834323650898f,-0.9238795325112867f},
  { 0.0f,-1.0f},
  { 0.3826834323650898f,-0.9238795325112867f},
  { 0.7071067811865476f,-0.7071067811865476f},
  { 0.9238795325112867f,-0.3826834323650898f}
};

// ---------------- complex helpers ----------------
__device__ __forceinline__ float2 cadd(float2 a, float2 b){ return make_float2(a.x+b.x, a.y+b.y); }
__device__ __forceinline__ float2 csub(float2 a, float2 b){ return make_float2(a.x-b.x, a.y-b.y); }
__device__ __forceinline__ float2 cmul(float2 a, float2 b){ return make_float2(a.x*b.x-a.y*b.y, a.x*b.y+a.y*b.x); }
template<int S> __device__ __forceinline__ float2 mul_i(float2 a){
  return (S>0) ? make_float2(-a.y, a.x) : make_float2(a.y, -a.x);
}
template<int S> __device__ __forceinline__ void dft4(float2&a, float2&b, float2&c, float2&d){
  float2 t0=cadd(a,c), t1=csub(a,c), t2=cadd(b,d), t3=mul_i<S>(csub(b,d));
  a=cadd(t0,t2); c=csub(t0,t2); b=cadd(t1,t3); d=csub(t1,t3);
}
template<int S> __device__ __forceinline__ float2 w16(int m){
  float2 w = W16T[m];
  if (S < 0) w.y = -w.y;
  return w;
}
template<int S> __device__ __forceinline__ void fft16(float2 v[16]){
  #pragma unroll
  for (int n0=0; n0<4; n0++) dft4<S>(v[n0], v[n0+4], v[n0+8], v[n0+12]);
  #pragma unroll
  for (int n0=1; n0<4; n0++)
    #pragma unroll
    for (int k1=1; k1<4; k1++)
      v[n0+4*k1] = cmul(v[n0+4*k1], w16<S>(n0*k1));
  float2 o[16];
  #pragma unroll
  for (int k1=0; k1<4; k1++){
    float2 a=v[4*k1+0], b=v[4*k1+1], c=v[4*k1+2], d=v[4*k1+3];
    dft4<S>(a,b,c,d);
    o[k1]=a; o[k1+4]=b; o[k1+8]=c; o[k1+12]=d;
  }
  #pragma unroll
  for (int i=0;i<16;i++) v[i]=o[i];
}

// padded-row transpose (conflict-free with FFT-slot f in LOW 4 bits of tid)
template<int S> __device__ __forceinline__ void fft256_pad(float2 v[16], int i, float2* sm){
  fft16<S>(v);
  #pragma unroll
  for (int k1=1;k1<16;k1++){
    float2 w = TW[(i*k1*256)&65535];
    if (S<0) w.y = -w.y;
    v[k1] = cmul(v[k1], w);
  }
  #pragma unroll
  for (int k1=0;k1<16;k1++) sm[k1*16+i] = v[k1];
  __syncthreads();
  #pragma unroll
  for (int n0=0;n0<16;n0++) v[n0] = sm[i*16+n0];
  fft16<S>(v);
}

// swizzled transpose (conflict-free with lane i in LOW 4 bits of tid)
template<int S> __device__ __forceinline__ void fft256_swz(float2 v[16], int i, float2* sm){
  fft16<S>(v);
  #pragma unroll
  for (int k1=1;k1<16;k1++){
    float2 w = TW[(i*k1*256)&65535];
    if (S<0) w.y = -w.y;
    v[k1] = cmul(v[k1], w);
  }
  #pragma unroll
  for (int k1=0;k1<16;k1++) sm[k1*16 + ((i+k1)&15)] = v[k1];
  __syncthreads();
  #pragma unroll
  for (int n0=0;n0<16;n0++) v[n0] = sm[i*16 + ((n0+i)&15)];
  fft16<S>(v);
}

// partial lowpass over this block's 16 stride-256 combs.
// u_s[f2*257 + n1] holds u[n1*256 + bx*16 + f2]. Thread m computes
// sum over f2,d of GF[d*256 + bx*16 + f2 + 768] * u[( (m+d)&255 )*256 + ...].
__device__ __forceinline__ void conv_partial(const float* u_s, const float* gf_s,
                                             int bx, int m, float* sp)
{
  float acc = 0.0f;
  #pragma unroll
  for (int f2=0; f2<16; f2++){
    const int q = bx*16 + f2 + 768;
    #pragma unroll
    for (int d=-3; d<=3; d++){
      int tap = d*256 + q;
      if (tap >= 0 && tap <= 1536)
        acc += gf_s[tap] * u_s[f2*257 + ((m + d) & 255)];
    }
  }
  sp[bx*256 + m] = acc;
}

// ---------------- setup kernels ----------------
__global__ void k_tw(){
  int k = blockIdx.x*blockDim.x + threadIdx.x;
  double a = 6.283185307179586476925286766559 * (double)k / 65536.0;
  TW[k] = make_float2((float)cos(a), (float)sin(a));
}
__global__ void k_g(){
  int i = blockIdx.x*blockDim.x + threadIdx.x;
  if (i >= GTAPS) return;
  int tt = i - LG; if (tt < 0) tt = -tt;
  const float invden = 1.0f/(65536.0f*(0.35f/256.0f));
  float acc = 1.0f;
  for (int k=1; k<=KPHI; k++){
    float z = (float)k * invden;
    float p = expf(-0.5f*z*z);
    int m = (k*tt) & 65535;
    acc += 2.0f * p * TW[m].x;
  }
  GF[i] = acc * INV_N;
}

// ---------------- FFT pass kernels ----------------
__global__ void __launch_bounds__(256) k_fwd_col_x(const float* __restrict__ x,
                                                   float2* __restrict__ out)
{
  __shared__ float2 sm[16*257];
  const int f = threadIdx.x & 15, i = threadIdx.x >> 4;
  const int col = blockIdx.x*16 + f;
  const size_t base = (size_t)blockIdx.y * NF;
  float2 v[16];
  #pragma unroll
  for (int r=0;r<16;r++) v[r] = make_float2(x[base + (r*16+i)*256 + col], 0.0f);
  fft256_pad<-1>(v, i, sm + f*257);
  #pragma unroll
  for (int k2=0;k2<16;k2++){
    int K1 = k2*16 + i;
    float2 w = TW[(col*K1)&65535]; w.y = -w.y;
    out[base + K1*256 + col] = cmul(v[k2], w);
  }
}

__global__ void __launch_bounds__(256) k_fwd_row(const float2* __restrict__ in,
                                                 float2* __restrict__ out)
{
  __shared__ float2 sm[16*256];
  const int i = threadIdx.x & 15, f = threadIdx.x >> 4;
  const int row = blockIdx.x*16 + f;
  const size_t base = (size_t)blockIdx.y * NF;
  float2 v[16];
  #pragma unroll
  for (int r=0;r<16;r++) v[r] = in[base + row*256 + r*16 + i];
  fft256_swz<-1>(v, i, sm + f*256);
  #pragma unroll
  for (int k2=0;k2<16;k2++) out[base + row*256 + k2*16 + i] = v[k2];
}

// Inverse pass A, fused pruned filter*1/N on load, inverse twiddle on store.
template<int FILT>
__global__ void __launch_bounds__(256) k_invA(const float2* __restrict__ in,
                                              float2* __restrict__ out)
{
  __shared__ float2 sm[16*256];
  const int i = threadIdx.x & 15, f = threadIdx.x >> 4;
  const int K1 = blockIdx.x*16 + f;
  const int ti = blockIdx.y;

  float xi, invs;
  const float2* src;
  if (FILT == 1){
    const int b = ti >> 6, ch = ti & 63;
    xi   = 0.35f * exp2f(-(float)ch * 0.125f);
    invs = 8.0f / xi;
    src  = in + (size_t)b*NF;
  } else {
    const int b = ti / NSEC;
    const int s0 = ti - b*NSEC;
    int j2 = 1;
    #pragma unroll
    for (int q=1; q<7; q++) if (s0 >= 4*q*(q+1)) j2 = q+1;
    const int ch = s0 - 4*j2*(j2-1);
    xi   = 0.35f * exp2f(-(float)j2);
    invs = 1.0f / (0.6f * xi);
    src  = in + ((size_t)b*JQ + ch)*NF;
  }

  float2 v[16];
  #pragma unroll
  for (int r=0;r<16;r++){
    int k2c = r*16 + i;
    int k = k2c*256 + K1;
    float fn = (k < 32768) ? (float)k * INV_N : ((float)k - 65536.0f) * INV_N;
    float z = (fn - xi) * invs;
    float g = expf(-0.5f*z*z);
    if (g > 1e-12f){
      float2 X = src[K1*256 + k2c];
      float s = g * INV_N;
      v[r] = make_float2(X.x*s, X.y*s);
    } else v[r] = make_float2(0.0f, 0.0f);
  }
  fft256_swz<1>(v, i, sm + f*256);
  #pragma unroll
  for (int k2=0;k2<16;k2++){
    int n2 = k2*16 + i;
    out[(size_t)ti*NF + K1*256 + n2] = cmul(v[k2], TW[(n2*K1)&65535]);
  }
}

// FO pass B: col IFFT -> |.| -> fused lowpass partial -> col FFT -> twiddle.
__global__ void __launch_bounds__(256) k_fo_b(const float2* __restrict__ T,
                                              float2* __restrict__ out,
                                              float* __restrict__ sp1)
{
  __shared__ __align__(16) char smraw[16*257*sizeof(float2)];
  float2* sm   = (float2*)smraw;
  float*  u_s  = (float*)smraw;             // 16*257 floats
  float*  gf_s = (float*)smraw + 16*257;    // 1537 floats (fits in 32.9KB)

  const int f = threadIdx.x & 15, i = threadIdx.x >> 4;
  const int tid = threadIdx.x;
  const int n2 = blockIdx.x*16 + f;
  const size_t base = (size_t)blockIdx.y * NF;
  float2 v[16];
  #pragma unroll
  for (int r=0;r<16;r++) v[r] = T[base + (r*16+i)*256 + n2];
  fft256_pad<1>(v, i, sm + f*257);
  __syncthreads();                           // sm reads done; reuse as u_s/gf_s
  #pragma unroll
  for (int k2=0;k2<16;k2++)
    u_s[f*257 + k2*16 + i] = sqrtf(v[k2].x*v[k2].x + v[k2].y*v[k2].y);
  for (int t=tid; t<GTAPS; t+=256) gf_s[t] = GF[t];
  __syncthreads();
  conv_partial(u_s, gf_s, blockIdx.x, tid, sp1 + (size_t)blockIdx.y*4096);
  __syncthreads();                           // partial reads done
  #pragma unroll
  for (int r=0;r<16;r++) v[r] = make_float2(u_s[f*257 + r*16 + i], 0.0f);
  __syncthreads();                           // u_s reads done; fft reuses sm
  fft256_pad<-1>(v, i, sm + f*257);
  #pragma unroll
  for (int k2=0;k2<16;k2++){
    int K1 = k2*16 + i;
    float2 w = TW[(n2*K1)&65535]; w.y = -w.y;
    out[base + K1*256 + n2] = cmul(v[k2], w);
  }
}

// SO pass B: col IFFT -> |.| -> fused lowpass partial. No u2 array.
__global__ void __launch_bounds__(256) k_invB_abs(const float2* __restrict__ T,
                                                  float* __restrict__ sp2)
{
  __shared__ __align__(16) char smraw[16*257*sizeof(float2)];
  float2* sm   = (float2*)smraw;
  float*  u_s  = (float*)smraw;
  float*  gf_s = (float*)smraw + 16*257;

  const int f = threadIdx.x & 15, i = threadIdx.x >> 4;
  const int tid = threadIdx.x;
  const int n2 = blockIdx.x*16 + f;
  const size_t base = (size_t)blockIdx.y * NF;
  float2 v[16];
  #pragma unroll
  for (int r=0;r<16;r++) v[r] = T[base + (r*16+i)*256 + n2];
  fft256_pad<1>(v, i, sm + f*257);
  __syncthreads();
  #pragma unroll
  for (int k2=0;k2<16;k2++)
    u_s[f*257 + k2*16 + i] = sqrtf(v[k2].x*v[k2].x + v[k2].y*v[k2].y);
  for (int t=tid; t<GTAPS; t+=256) gf_s[t] = GF[t];
  __syncthreads();
  conv_partial(u_s, gf_s, blockIdx.x, tid, sp2 + (size_t)blockIdx.y*4096);
}

// ---------------- S0 conv (x only) ----------------
#define CONV_OUT 32
#define CONV_WIN ((CONV_OUT-1)*256 + GTAPS)   // 9473
__global__ void __launch_bounds__(256) k_conv_x(const float* __restrict__ x,
                                                float* __restrict__ out)
{
  const int grp = blockIdx.x, b = blockIdx.y;
  const float* src = x + (size_t)b*NF;
  __shared__ float win[CONV_WIN + 3];
  __shared__ float gs[GTAPS];
  const int tid = threadIdx.x;
  const int w0 = grp*(CONV_OUT*256) - LG;
  for (int i=tid; i<CONV_WIN; i+=256) win[i] = src[(w0 + i) & 65535];
  for (int i=tid; i<GTAPS; i+=256) gs[i] = GF[i];
  __syncthreads();
  const int warp = tid >> 5, lane = tid & 31;
  #pragma unroll
  for (int oo=0; oo<CONV_OUT/8; oo++){
    const int o = warp*(CONV_OUT/8) + oo;
    const int off = o * 256;
    float acc = 0.0f;
    for (int i=lane; i<GTAPS; i+=32) acc += gs[i] * win[off + i];
    #pragma unroll
    for (int d=16; d; d>>=1) acc += __shfl_down_sync(0xffffffffu, acc, d);
    if (lane == 0){
      int n = grp*CONV_OUT + o;
      float mag = sqrtf(acc*acc + 1e-8f);
      out[(size_t)b*NCHAN*256 + n] = logf(mag + 1e-8f);
    }
  }
}

// ---------------- epilogue: sum 16 partials, log ----------------
__global__ void __launch_bounds__(256) k_log(const float* __restrict__ sp1,
                                             const float* __restrict__ sp2,
                                             float* __restrict__ out)
{
  const int row = blockIdx.x;                // 0..2303 = b*288 + (c-1)
  const int b = row / 288, cm1 = row - b*288;
  const int m = threadIdx.x;
  const float* base = (cm1 < 64)
    ? sp1 + (size_t)(b*JQ   + cm1     )*4096
    : sp2 + (size_t)(b*NSEC + cm1 - 64)*4096;
  float S = 0.0f;
  #pragma unroll
  for (int k=0;k<16;k++) S += base[k*256 + m];
  float mag = sqrtf(S*S + 1e-8f);
  out[((size_t)b*NCHAN + 1 + cm1)*256 + m] = logf(mag + 1e-8f);
}

__global__ void k_zero(float* p, int n){
  int i = blockIdx.x*blockDim.x + threadIdx.x;
  if (i < n) p[i] = 0.0f;
}

// ---------------- launch ----------------
extern "C" void kernel_launch(void* const* d_in, const int* in_sizes, int n_in,
                              void* d_out, int out_size)
{
  (void)in_sizes; (void)n_in;
  const float* x = (const float*)d_in[0];
  float* out = (float*)d_out;

  float2 *xf, *ping, *pong, *u1f;
  float *sp1, *sp2;
  cudaGetSymbolAddress((void**)&xf,   d_xf);
  cudaGetSymbolAddress((void**)&ping, d_ping);
  cudaGetSymbolAddress((void**)&pong, d_pong);
  cudaGetSymbolAddress((void**)&u1f,  d_u1f);
  cudaGetSymbolAddress((void**)&sp1,  d_sp1);
  cudaGetSymbolAddress((void**)&sp2,  d_sp2);

  k_tw<<<256, 256>>>();
  k_g <<<7,   256>>>();

  // forward FFT of x (8 transforms)
  k_fwd_col_x<<<dim3(16,8),    256>>>(x, ping);
  k_fwd_row  <<<dim3(16,8),    256>>>(ping, xf);

  // first order: filtered IFFT passA; passB fused with |.|, lowpass partial, fwd col FFT
  k_invA<1>  <<<dim3(16,512),  256>>>(xf, ping);
  k_fo_b     <<<dim3(16,512),  256>>>(ping, pong, sp1);
  k_fwd_row  <<<dim3(16,512),  256>>>(pong, u1f);

  // second order: filtered IFFT passA; passB fused with |.| and lowpass partial
  k_invA<2>  <<<dim3(16,1792), 256>>>(u1f, ping);
  k_invB_abs <<<dim3(16,1792), 256>>>(ping, sp2);

  // S0 + epilogue
  k_conv_x<<<dim3(8, NB), 256>>>(x, out);
  k_log   <<<2304, 256>>>(sp1, sp2, out);

  // imaginary half = zeros
  int half = out_size / 2;
  k_zero<<<(half + 255)/256, 256>>>(out + half, half);
}